// round 9
// baseline (speedup 1.0000x reference)
#include <cuda_runtime.h>
#include <cuda_fp16.h>
#include <math.h>
#include <stdint.h>

#define NN   100000
#define FIN  256
#define FH   50
#define FHP  52        // padded hidden width
#define FOUT 40
#define EE   3200000
#define ET   (EE + NN) // edges + self loops

#define SCAN_BS 512
#define SCAN_NB ((NN + SCAN_BS - 1) / SCAN_BS)   // 196

// ---------------- scratch (device globals; no allocation) ----------------
__device__ __align__(16) __half g_h1h[NN * FHP]; // x@W1+b1 in fp16 (pads zero)
__device__ __align__(16) __half g_h2h[NN * FOUT];// layer2 pre-agg, fp16
__device__ int   g_degi[NN];                     // EXTRA degree (self-loop implied +1); reset by scanC
__device__ int   g_cursor[NN];                   // seeded to g_off in scanC
__device__ float g_dinv[NN];
__device__ int   g_off[NN + 1];                  // CSR offsets (exclusive)
__device__ int   g_bsum[SCAN_NB];
__device__ int   g_boff[SCAN_NB];
__device__ int   g_adj[ET];                      // source row only (4B/edge)

// ---------------- prep: count in-degree of real edges (4 per thread) ------
__global__ void prep_kernel(const int* __restrict__ ei) {
    int t = blockIdx.x * blockDim.x + threadIdx.x;
    if (t >= EE / 4) return;
    int4 c4 = *reinterpret_cast<const int4*>(ei + EE + 4 * t);
    int c;
    c = c4.x; if ((unsigned)c >= NN) c = 0; atomicAdd(&g_degi[c], 1);
    c = c4.y; if ((unsigned)c >= NN) c = 0; atomicAdd(&g_degi[c], 1);
    c = c4.z; if ((unsigned)c >= NN) c = 0; atomicAdd(&g_degi[c], 1);
    c = c4.w; if ((unsigned)c >= NN) c = 0; atomicAdd(&g_degi[c], 1);
}

// ---------------- scan A: per-block sums of (degi + 1) ---------------------
__global__ void scanA_kernel() {
    __shared__ int s[SCAN_BS];
    int tid = threadIdx.x;
    int i = blockIdx.x * SCAN_BS + tid;
    s[tid] = (i < NN) ? (g_degi[i] + 1) : 0;
    __syncthreads();
    for (int st = SCAN_BS / 2; st > 0; st >>= 1) {
        if (tid < st) s[tid] += s[tid + st];
        __syncthreads();
    }
    if (tid == 0) g_bsum[blockIdx.x] = s[0];
}

// ---------------- scan B: parallel exclusive scan of block sums ------------
__global__ void scanB_kernel() {
    __shared__ int s[256];
    int tid = threadIdx.x;
    int v = (tid < SCAN_NB) ? g_bsum[tid] : 0;
    s[tid] = v;
    __syncthreads();
    for (int off = 1; off < 256; off <<= 1) {
        int add = (tid >= off) ? s[tid - off] : 0;
        __syncthreads();
        s[tid] += add;
        __syncthreads();
    }
    if (tid < SCAN_NB) g_boff[tid] = s[tid] - v;   // exclusive
    if (tid == 0) g_off[NN] = ET;
}

// ---------------- scan C: exclusive scan + dinv + cursor seed + degi reset -
__global__ void scanC_kernel() {
    __shared__ int s[SCAN_BS];
    int tid = threadIdx.x;
    int i = blockIdx.x * SCAN_BS + tid;
    int v = (i < NN) ? (g_degi[i] + 1) : 0;
    s[tid] = v;
    __syncthreads();
    for (int off = 1; off < SCAN_BS; off <<= 1) {
        int t = s[tid];
        int add = (tid >= off) ? s[tid - off] : 0;
        __syncthreads();
        s[tid] = t + add;
        __syncthreads();
    }
    if (i < NN) {
        int off = g_boff[blockIdx.x] + s[tid] - v;   // exclusive
        g_off[i] = off;
        g_cursor[i] = off;                            // fill uses absolute slots
        g_dinv[i] = rsqrtf((float)v);                 // v >= 1 (self-loop)
        g_degi[i] = 0;                                // ready for next call
    }
}

// ---------------- fill CSR slots (2 edges/thread + self-loop tail) ---------
__global__ void fill_kernel(const int* __restrict__ ei) {
    int t = blockIdx.x * blockDim.x + threadIdx.x;
    if (t < EE / 2) {
        int2 r2 = *reinterpret_cast<const int2*>(ei + 2 * t);
        int2 c2 = *reinterpret_cast<const int2*>(ei + EE + 2 * t);
        int r0 = r2.x, c0 = c2.x, r1 = r2.y, c1 = c2.y;
        if ((unsigned)r0 >= NN) r0 = 0;
        if ((unsigned)c0 >= NN) c0 = 0;
        if ((unsigned)r1 >= NN) r1 = 0;
        if ((unsigned)c1 >= NN) c1 = 0;
        g_adj[atomicAdd(&g_cursor[c0], 1)] = r0;
        g_adj[atomicAdd(&g_cursor[c1], 1)] = r1;
    } else {
        int n = t - EE / 2;
        if (n < NN)
            g_adj[atomicAdd(&g_cursor[n], 1)] = n;   // self loop
    }
}

// ---------------- GEMM1 (tf32 tensor cores): h1 = x @ W1 + b1 (fp16 out) ---
__device__ __forceinline__ uint32_t f2tf32(float f) {
    uint32_t u;
    asm("cvt.rna.tf32.f32 %0, %1;" : "=r"(u) : "f"(f));
    return u;
}

__global__ void gemm1_tf32_kernel(const float* __restrict__ x,
                                  const float* __restrict__ W,
                                  const float* __restrict__ b) {
    __shared__ uint32_t Xs[128][20];   // pitch 20: conflict-free frag loads
    __shared__ uint32_t Ws[16][72];    // pitch 72: conflict-free frag loads
    __shared__ float bs[64];

    int tid = threadIdx.x;
    int lane = tid & 31;
    int warp = tid >> 5;
    int wm = warp & 3;
    int wn = warp >> 2;
    int rowBase = blockIdx.x * 128;

    if (tid < 64) bs[tid] = (tid < FH) ? b[tid] : 0.f;

    float acc[2][4][4];
#pragma unroll
    for (int mt = 0; mt < 2; mt++)
#pragma unroll
        for (int nt = 0; nt < 4; nt++)
#pragma unroll
            for (int q = 0; q < 4; q++) acc[mt][nt][q] = 0.f;

    for (int k0 = 0; k0 < FIN; k0 += 16) {
        {
            int r = tid >> 2;
            int cs = (tid & 3) * 4;
#pragma unroll
            for (int i = 0; i < 2; i++) {
                int row = i * 64 + r;
                int grow = rowBase + row;
                float4 xv = make_float4(0.f, 0.f, 0.f, 0.f);
                if (grow < NN)
                    xv = *reinterpret_cast<const float4*>(x + grow * FIN + k0 + cs);
                Xs[row][cs + 0] = f2tf32(xv.x);
                Xs[row][cs + 1] = f2tf32(xv.y);
                Xs[row][cs + 2] = f2tf32(xv.z);
                Xs[row][cs + 3] = f2tf32(xv.w);
            }
        }
        {
#pragma unroll
            for (int i = 0; i < 4; i++) {
                int idx = i * 256 + tid;
                int kk = idx >> 6;
                int c = idx & 63;
                float wv = (c < FH) ? W[(k0 + kk) * FH + c] : 0.f;
                Ws[kk][c] = f2tf32(wv);
            }
        }
        __syncthreads();

#pragma unroll
        for (int ks = 0; ks < 16; ks += 8) {
            uint32_t a[2][4];
#pragma unroll
            for (int mt = 0; mt < 2; mt++) {
                int r = wm * 32 + mt * 16 + (lane >> 2);
                int c = ks + (lane & 3);
                a[mt][0] = Xs[r][c];
                a[mt][1] = Xs[r + 8][c];
                a[mt][2] = Xs[r][c + 4];
                a[mt][3] = Xs[r + 8][c + 4];
            }
#pragma unroll
            for (int nt = 0; nt < 4; nt++) {
                int n = wn * 32 + nt * 8 + (lane >> 2);
                int kb = ks + (lane & 3);
                uint32_t b0 = Ws[kb][n];
                uint32_t b1 = Ws[kb + 4][n];
#pragma unroll
                for (int mt = 0; mt < 2; mt++) {
                    asm volatile(
                        "mma.sync.aligned.m16n8k8.row.col.f32.tf32.tf32.f32 "
                        "{%0,%1,%2,%3}, {%4,%5,%6,%7}, {%8,%9}, {%0,%1,%2,%3};"
                        : "+f"(acc[mt][nt][0]), "+f"(acc[mt][nt][1]),
                          "+f"(acc[mt][nt][2]), "+f"(acc[mt][nt][3])
                        : "r"(a[mt][0]), "r"(a[mt][1]), "r"(a[mt][2]), "r"(a[mt][3]),
                          "r"(b0), "r"(b1));
                }
            }
        }
        __syncthreads();
    }

    // epilogue: packed half2 stores; cols are even pairs so 50-boundary is clean
#pragma unroll
    for (int mt = 0; mt < 2; mt++) {
#pragma unroll
        for (int nt = 0; nt < 4; nt++) {
            int row0 = rowBase + wm * 32 + mt * 16 + (lane >> 2);
            int col0 = wn * 32 + nt * 8 + 2 * (lane & 3);   // even
            if (col0 >= FHP) continue;
#pragma unroll
            for (int h = 0; h < 2; h++) {
                int row = row0 + h * 8;
                if (row >= NN) continue;
                __half2 hv;
                if (col0 < FH) {
                    hv = __floats2half2_rn(acc[mt][nt][h * 2 + 0] + bs[col0],
                                           acc[mt][nt][h * 2 + 1] + bs[col0 + 1]);
                } else {
                    hv = __floats2half2_rn(0.f, 0.f);       // pad cols 50,51
                }
                *reinterpret_cast<__half2*>(g_h1h + row * FHP + col0) = hv;
            }
        }
    }
}

// ---------------- agg1 + gemm2 fused -----------------------------------------
// 512 threads = 32 nodes x 16 lanes. Phase 1: lanes 0..12 gather/aggregate the
// fp16 h1 rows into a1 (relu'd) staged in smem. Phase 2: lanes 0..9 compute
// h2 = a1 @ W2 + b2 from smem and store packed fp16.
__global__ __launch_bounds__(512) void agg1_gemm2_kernel(
        const float* __restrict__ W, const float* __restrict__ b) {
    __shared__ float W2s[FH * FOUT];   // 8000B
    __shared__ float bs[FOUT];
    __shared__ float a1s[32][FHP];     // 32 nodes x 52 floats

    int tid = threadIdx.x;
    for (int i = tid; i < FH * FOUT; i += 512) W2s[i] = W[i];
    if (tid < FOUT) bs[tid] = b[tid];
    __syncthreads();

    int node = (blockIdx.x * 512 + tid) >> 4;   // grid sized exactly: node < NN
    int grp = tid >> 4;                          // 0..31 node slot in block
    int ch = tid & 15;

    // ---- phase 1: aggregate ----
    if (ch < 13) {
        int j = g_off[node];
        int end = g_off[node + 1];
        float4 acc = make_float4(0.f, 0.f, 0.f, 0.f);
        float4 acc2 = make_float4(0.f, 0.f, 0.f, 0.f);

        for (; j + 1 < end; j += 2) {
            int r0 = g_adj[j];
            int r1 = g_adj[j + 1];
            float d0 = g_dinv[r0];
            float d1 = g_dinv[r1];
            uint2 u0 = __ldg(reinterpret_cast<const uint2*>(g_h1h + r0 * FHP + ch * 4));
            uint2 u1 = __ldg(reinterpret_cast<const uint2*>(g_h1h + r1 * FHP + ch * 4));
            float2 a0 = __half22float2(*reinterpret_cast<__half2*>(&u0.x));
            float2 b0 = __half22float2(*reinterpret_cast<__half2*>(&u0.y));
            float2 a1 = __half22float2(*reinterpret_cast<__half2*>(&u1.x));
            float2 b1 = __half22float2(*reinterpret_cast<__half2*>(&u1.y));
            acc.x  += d0 * a0.x; acc.y  += d0 * a0.y; acc.z  += d0 * b0.x; acc.w  += d0 * b0.y;
            acc2.x += d1 * a1.x; acc2.y += d1 * a1.y; acc2.z += d1 * b1.x; acc2.w += d1 * b1.y;
        }
        if (j < end) {
            int r0 = g_adj[j];
            float d0 = g_dinv[r0];
            uint2 u0 = __ldg(reinterpret_cast<const uint2*>(g_h1h + r0 * FHP + ch * 4));
            float2 a0 = __half22float2(*reinterpret_cast<__half2*>(&u0.x));
            float2 b0 = __half22float2(*reinterpret_cast<__half2*>(&u0.y));
            acc.x += d0 * a0.x; acc.y += d0 * a0.y; acc.z += d0 * b0.x; acc.w += d0 * b0.y;
        }
        float dc = g_dinv[node];
        a1s[grp][ch * 4 + 0] = fmaxf(dc * (acc.x + acc2.x), 0.f);
        a1s[grp][ch * 4 + 1] = fmaxf(dc * (acc.y + acc2.y), 0.f);
        a1s[grp][ch * 4 + 2] = fmaxf(dc * (acc.z + acc2.z), 0.f);
        a1s[grp][ch * 4 + 3] = fmaxf(dc * (acc.w + acc2.w), 0.f);
    }
    __syncwarp();

    // ---- phase 2: gemm2 row from smem ----
    if (ch < 10) {
        int c0 = ch * 4;
        float o0 = bs[c0], o1 = bs[c0 + 1], o2 = bs[c0 + 2], o3 = bs[c0 + 3];
#pragma unroll 10
        for (int k = 0; k < FH; k++) {
            float v = a1s[grp][k];                 // broadcast across lanes
            const float* wr = &W2s[k * FOUT + c0];
            o0 += v * wr[0];
            o1 += v * wr[1];
            o2 += v * wr[2];
            o3 += v * wr[3];
        }
        __half2 p0 = __floats2half2_rn(o0, o1);
        __half2 p1 = __floats2half2_rn(o2, o3);
        uint2 u;
        u.x = *reinterpret_cast<uint32_t*>(&p0);
        u.y = *reinterpret_cast<uint32_t*>(&p1);
        *reinterpret_cast<uint2*>(g_h2h + node * FOUT + c0) = u;
    }
}

// ---------------- agg2 + log_softmax fused (fp16 gather) -------------------
__global__ void agg2_ls_kernel(float* __restrict__ out) {
    int t = blockIdx.x * blockDim.x + threadIdx.x;
    int node = t >> 4;
    int ch = t & 15;
    bool valid = (node < NN);
    bool act = valid && (ch < 10);

    float4 acc = make_float4(0.f, 0.f, 0.f, 0.f);
    float4 acc2 = make_float4(0.f, 0.f, 0.f, 0.f);

    if (act) {
        int j = g_off[node];
        int end = g_off[node + 1];
        for (; j + 1 < end; j += 2) {
            int r0 = g_adj[j];
            int r1 = g_adj[j + 1];
            float d0 = g_dinv[r0];
            float d1 = g_dinv[r1];
            uint2 u0 = __ldg(reinterpret_cast<const uint2*>(g_h2h + r0 * FOUT + ch * 4));
            uint2 u1 = __ldg(reinterpret_cast<const uint2*>(g_h2h + r1 * FOUT + ch * 4));
            float2 a0 = __half22float2(*reinterpret_cast<__half2*>(&u0.x));
            float2 b0 = __half22float2(*reinterpret_cast<__half2*>(&u0.y));
            float2 a1 = __half22float2(*reinterpret_cast<__half2*>(&u1.x));
            float2 b1 = __half22float2(*reinterpret_cast<__half2*>(&u1.y));
            acc.x  += d0 * a0.x; acc.y  += d0 * a0.y; acc.z  += d0 * b0.x; acc.w  += d0 * b0.y;
            acc2.x += d1 * a1.x; acc2.y += d1 * a1.y; acc2.z += d1 * b1.x; acc2.w += d1 * b1.y;
        }
        if (j < end) {
            int r0 = g_adj[j];
            float d0 = g_dinv[r0];
            uint2 u0 = __ldg(reinterpret_cast<const uint2*>(g_h2h + r0 * FOUT + ch * 4));
            float2 a0 = __half22float2(*reinterpret_cast<__half2*>(&u0.x));
            float2 b0 = __half22float2(*reinterpret_cast<__half2*>(&u0.y));
            acc.x += d0 * a0.x; acc.y += d0 * a0.y; acc.z += d0 * b0.x; acc.w += d0 * b0.y;
        }
        float dc = g_dinv[node];
        acc.x = dc * (acc.x + acc2.x);
        acc.y = dc * (acc.y + acc2.y);
        acc.z = dc * (acc.z + acc2.z);
        acc.w = dc * (acc.w + acc2.w);
    }

    float m = act ? fmaxf(fmaxf(acc.x, acc.y), fmaxf(acc.z, acc.w)) : -INFINITY;
#pragma unroll
    for (int d = 8; d > 0; d >>= 1)
        m = fmaxf(m, __shfl_down_sync(0xffffffffu, m, d, 16));
    m = __shfl_sync(0xffffffffu, m, 0, 16);

    float s = act ? (expf(acc.x - m) + expf(acc.y - m) + expf(acc.z - m) + expf(acc.w - m)) : 0.f;
#pragma unroll
    for (int d = 8; d > 0; d >>= 1)
        s += __shfl_down_sync(0xffffffffu, s, d, 16);
    s = __shfl_sync(0xffffffffu, s, 0, 16);

    float l = m + logf(s);
    if (act) {
        *reinterpret_cast<float4*>(out + node * FOUT + ch * 4) =
            make_float4(acc.x - l, acc.y - l, acc.z - l, acc.w - l);
    }
}

// ---------------- launch (single stream) -----------------------------------
extern "C" void kernel_launch(void* const* d_in, const int* in_sizes, int n_in,
                              void* d_out, int out_size) {
    const float* x   = (const float*)d_in[0];
    const int*   ei  = (const int*)d_in[1];   // int32 (JAX x64 disabled)
    const float* W1  = (const float*)d_in[2];
    const float* b1  = (const float*)d_in[3];
    const float* W2  = (const float*)d_in[4];
    const float* b2  = (const float*)d_in[5];
    float*       out = (float*)d_out;

    const int T = 256;

    // CSR build (g_degi starts zero: static init on call 1, scanC reset after)
    prep_kernel<<<(EE / 4 + T - 1) / T, T>>>(ei);
    scanA_kernel<<<SCAN_NB, SCAN_BS>>>();
    scanB_kernel<<<1, 256>>>();
    scanC_kernel<<<SCAN_NB, SCAN_BS>>>();
    fill_kernel<<<(EE / 2 + NN + T - 1) / T, T>>>(ei);

    // layer 1
    gemm1_tf32_kernel<<<(NN + 127) / 128, T>>>(x, W1, b1);

    // layer 1 aggregation + layer 2 transform (fused)
    agg1_gemm2_kernel<<<(NN * 16) / 512, 512>>>(W2, b2);

    // layer 2 aggregation + log softmax
    agg2_ls_kernel<<<(NN * 16 + T - 1) / T, T>>>(out);
}